// round 16
// baseline (speedup 1.0000x reference)
#include <cuda_runtime.h>
#include <cstdint>
#include <math.h>

// Shapes
#define BATCH 64
#define FEAT  2048
#define EDIM  64

// 16 batch groups x 8 feature chunks = 128 CTAs; each 8-CTA cluster covers one
// batch group (4 rows), combines partials in the leader's SMEM via DSMEM.
#define NB_ROWS 4
#define CLUSTER 8
#define FCHUNK  (FEAT / CLUSTER)                 // 256
#define GRID    ((BATCH / NB_ROWS) * CLUSTER)    // 128
#define NTHREADS 256                             // 16 fg x 16 dq

__device__ __forceinline__ uint32_t smem_u32(const void* p) {
    uint32_t a;
    asm("{ .reg .u64 t; cvta.to.shared.u64 t, %1; cvt.u32.u64 %0, t; }"
        : "=r"(a) : "l"(p));
    return a;
}

// Store one f32 into cluster-rank-0's SMEM at the same offset as `local_addr`.
__device__ __forceinline__ void dsmem_st_leader_f32(uint32_t local_addr, float v) {
    uint32_t remote;
    asm volatile("mapa.shared::cluster.u32 %0, %1, 0;" : "=r"(remote) : "r"(local_addr));
    asm volatile("st.shared::cluster.f32 [%0], %1;" :: "r"(remote), "f"(v) : "memory");
}

__global__ void __cluster_dims__(CLUSTER, 1, 1) __launch_bounds__(NTHREADS, 1)
fm_cluster(const float* __restrict__ data,    // (BATCH, FEAT)
           const float* __restrict__ embed,   // (FEAT, EDIM)
           const float* __restrict__ bias,    // (FEAT,)
           const float* __restrict__ gbias,   // (1,)
           float* __restrict__ out)           // (BATCH,)
{
    __shared__ float sh_x[NB_ROWS][FCHUNK];          //  4 KB
    __shared__ float shp[16][NB_ROWS][EDIM + 4];     // ~17 KB (pad: align + banks)
    __shared__ float red_S[CLUSTER][NB_ROWS][EDIM];  //  8 KB  (leader receives)
    __shared__ float red_L[CLUSTER][NB_ROWS];        //  128 B (leader receives)
    __shared__ float linT[NB_ROWS][2];
    __shared__ float fin[NB_ROWS][2];

    const int tid = threadIdx.x;
    uint32_t rank;
    asm("mov.u32 %0, %%cluster_ctarank;" : "=r"(rank));
    const int bg = blockIdx.x / CLUSTER;   // batch group 0..15
    const int fc = (int)rank;              // feature chunk 0..7
    const int b0 = bg * NB_ROWS;
    const int f0 = fc * FCHUNK;

    const int fg = tid >> 4;       // 0..15, 16 features each
    const int dq = tid & 15;       // 0..15
    const int d0 = dq * 4;
    const int r  = tid >> 6;       // 0..3 (x-loader row)
    const int c  = tid & 63;       // 0..63

    // --- FIRST in the LSU queue: the loads that gate the first barrier.
    // L1tex completion is queue-position ordered; putting x/bias/gbias ahead
    // of the 16 embed LDG.128s shortens the time-to-sync by ~the embed queue
    // depth. Embed data isn't consumed until after the sync anyway. ---
    const float4 x4 = *reinterpret_cast<const float4*>(&data[(b0 + r) * FEAT + f0 + c * 4]);
    const float4 bb = *reinterpret_cast<const float4*>(&bias[f0 + c * 4]);
    const float  gb = __ldg(gbias);   // hoisted off the leader's exit chain

    // --- Embed prefetch into registers (needed only post-sync). ---
    float4 v[16];
#pragma unroll
    for (int j = 0; j < 16; j++) {
        const int fl = fg * 16 + j;
        v[j] = *reinterpret_cast<const float4*>(&embed[(f0 + fl) * EDIM + d0]);
    }

    // --- Stage x into shared + fold the bias dot-product (linear term). ---
    *reinterpret_cast<float4*>(&sh_x[r][c * 4]) = x4;
    {
        float p = x4.x * bb.x + x4.y * bb.y + x4.z * bb.z + x4.w * bb.w;
#pragma unroll
        for (int o = 16; o; o >>= 1) p += __shfl_xor_sync(0xffffffffu, p, o);
        if ((tid & 31) == 0) linT[r][(tid >> 5) & 1] = p;
    }
    __syncthreads();

    // --- Partial GEMM from registers: each prefetched float4 feeds 16 FFMA. ---
    float acc[NB_ROWS][4];
#pragma unroll
    for (int rr = 0; rr < NB_ROWS; rr++)
#pragma unroll
        for (int i = 0; i < 4; i++) acc[rr][i] = 0.0f;

#pragma unroll
    for (int j = 0; j < 16; j++) {
        const int fl = fg * 16 + j;
#pragma unroll
        for (int rr = 0; rr < NB_ROWS; rr++) {
            const float xf = sh_x[rr][fl];
            acc[rr][0] = fmaf(xf, v[j].x, acc[rr][0]);
            acc[rr][1] = fmaf(xf, v[j].y, acc[rr][1]);
            acc[rr][2] = fmaf(xf, v[j].z, acc[rr][2]);
            acc[rr][3] = fmaf(xf, v[j].w, acc[rr][3]);
        }
    }

#pragma unroll
    for (int rr = 0; rr < NB_ROWS; rr++) {
        float4 w;
        w.x = acc[rr][0]; w.y = acc[rr][1]; w.z = acc[rr][2]; w.w = acc[rr][3];
        *reinterpret_cast<float4*>(&shp[fg][rr][d0]) = w;
    }
    __syncthreads();

    // --- Cross-fg reduce -> partial S; ship to leader (plain STS if leader). ---
    {
        float s = 0.0f;
#pragma unroll
        for (int g = 0; g < 16; g++) s += shp[g][r][c];
        if (rank == 0) red_S[fc][r][c] = s;
        else           dsmem_st_leader_f32(smem_u32(&red_S[fc][r][c]), s);
    }
    if (tid < NB_ROWS) {
        const float l = linT[tid][0] + linT[tid][1];
        if (rank == 0) red_L[fc][tid] = l;
        else           dsmem_st_leader_f32(smem_u32(&red_L[fc][tid]), l);
    }

    // --- Combine sync: each thread's arrive releases its own DSMEM stores.
    // Non-leaders arrive and EXIT; only the leader waits (doubles as its
    // CTA-wide barrier before reading red_S/red_L). ---
    asm volatile("barrier.cluster.arrive.aligned;" ::: "memory");
    if (rank != 0) return;
    asm volatile("barrier.cluster.wait.aligned;"   ::: "memory");

    // --- Leader epilogue: combine 8 chunk-partials, square-sum over d,
    // add linear + global bias, sigmoid. ---
    {
        float s = 0.0f;
#pragma unroll
        for (int k = 0; k < CLUSTER; k++) s += red_S[k][r][c];
        float sq = s * s;
#pragma unroll
        for (int o = 16; o; o >>= 1) sq += __shfl_xor_sync(0xffffffffu, sq, o);
        if ((tid & 31) == 0) fin[r][(tid >> 5) & 1] = sq;
    }
    __syncthreads();

    if (tid < NB_ROWS) {
        float lin = 0.0f;
#pragma unroll
        for (int k = 0; k < CLUSTER; k++) lin += red_L[k][tid];
        const float z = gb + lin + fin[tid][0] + fin[tid][1];
        out[b0 + tid] = 1.0f / (1.0f + __expf(-z));
    }
}

extern "C" void kernel_launch(void* const* d_in, const int* in_sizes, int n_in,
                              void* d_out, int out_size) {
    const float* data  = (const float*)d_in[0];
    const float* embed = (const float*)d_in[1];
    const float* bias  = (const float*)d_in[2];
    const float* gbias = (const float*)d_in[3];
    float* out = (float*)d_out;

    fm_cluster<<<GRID, NTHREADS>>>(data, embed, bias, gbias, out);
}

// round 17
// speedup vs baseline: 2.4480x; 2.4480x over previous
#include <cuda_runtime.h>
#include <cstdint>
#include <math.h>

// Shapes
#define BATCH 64
#define FEAT  2048
#define EDIM  64

// 16 batch groups x 8 feature chunks = 128 CTAs; each 8-CTA cluster covers one
// batch group (4 rows). Partials combine in the leader's SMEM via DSMEM; the
// handshake is a leader-hosted mbarrier (count=7) instead of a full cluster
// barrier -> leader wakeup ~60-90cyc instead of ~490cyc UCGABAR_WAIT, and the
// 7 producers exit without waiting at all.
#define NB_ROWS 4
#define CLUSTER 8
#define FCHUNK  (FEAT / CLUSTER)                 // 256
#define GRID    ((BATCH / NB_ROWS) * CLUSTER)    // 128
#define NTHREADS 256                             // 16 fg x 16 dq

__device__ __forceinline__ uint32_t smem_u32(const void* p) {
    uint32_t a;
    asm("{ .reg .u64 t; cvta.to.shared.u64 t, %1; cvt.u32.u64 %0, t; }"
        : "=r"(a) : "l"(p));
    return a;
}

// Store one f32 into cluster-rank-0's SMEM at the same offset as `local_addr`.
__device__ __forceinline__ void dsmem_st_leader_f32(uint32_t local_addr, float v) {
    uint32_t remote;
    asm volatile("mapa.shared::cluster.u32 %0, %1, 0;" : "=r"(remote) : "r"(local_addr));
    asm volatile("st.shared::cluster.f32 [%0], %1;" :: "r"(remote), "f"(v) : "memory");
}

// Single release-arrive on the LEADER's mbarrier (cluster scope). Release
// cumulativity + the preceding __syncthreads() publishes this CTA's DSMEM
// stores to the leader's subsequent acquire-wait.
__device__ __forceinline__ void mbar_arrive_leader(uint32_t local_mbar) {
    asm volatile(
        "{\n\t.reg .b32 ra;\n\t"
        "mapa.shared::cluster.u32 ra, %0, 0;\n\t"
        "mbarrier.arrive.release.cluster.shared::cluster.b64 _, [ra];\n\t}"
        :: "r"(local_mbar) : "memory");
}

// Parity-0 wait with cluster-scope acquire (covers peer-CTA DSMEM stores).
__device__ __forceinline__ void mbar_wait_p0_cluster(uint32_t mbar) {
    uint32_t done;
    asm volatile(
        "{\n\t.reg .pred p;\n\t"
        "mbarrier.try_wait.parity.acquire.cluster.shared::cta.b64 p, [%1], 0;\n\t"
        "selp.b32 %0, 1, 0, p;\n\t}"
        : "=r"(done) : "r"(mbar) : "memory");
    if (!done) {
        asm volatile(
            "{\n\t.reg .pred P1;\n\t"
            "WL_%=:\n\t"
            "mbarrier.try_wait.parity.acquire.cluster.shared::cta.b64 P1, [%0], 0, 0x989680;\n\t"
            "@P1 bra.uni WD_%=;\n\t"
            "bra.uni WL_%=;\n\t"
            "WD_%=:\n\t}"
            :: "r"(mbar) : "memory");
    }
}

__global__ void __cluster_dims__(CLUSTER, 1, 1) __launch_bounds__(NTHREADS, 1)
fm_cluster(const float* __restrict__ data,    // (BATCH, FEAT)
           const float* __restrict__ embed,   // (FEAT, EDIM)
           const float* __restrict__ bias,    // (FEAT,)
           const float* __restrict__ gbias,   // (1,)
           float* __restrict__ out)           // (BATCH,)
{
    __shared__ float sh_x[NB_ROWS][FCHUNK];          //  4 KB
    __shared__ float shp[16][NB_ROWS][EDIM + 4];     // ~17 KB (pad: align + banks)
    __shared__ float red_S[CLUSTER][NB_ROWS][EDIM];  //  8 KB  (leader receives)
    __shared__ float red_L[CLUSTER][NB_ROWS];        //  128 B (leader receives)
    __shared__ float linT[NB_ROWS][2];
    __shared__ float fin[NB_ROWS][2];
    __shared__ __align__(8) uint64_t mbar;           // leader's combine barrier

    const int tid = threadIdx.x;
    uint32_t rank;
    asm("mov.u32 %0, %%cluster_ctarank;" : "=r"(rank));
    const int bg = blockIdx.x / CLUSTER;   // batch group 0..15
    const int fc = (int)rank;              // feature chunk 0..7
    const int b0 = bg * NB_ROWS;
    const int f0 = fc * FCHUNK;

    const int fg = tid >> 4;       // 0..15, 16 features each
    const int dq = tid & 15;       // 0..15
    const int d0 = dq * 4;
    const int r  = tid >> 6;       // 0..3 (x-loader row)
    const int c  = tid & 63;       // 0..63

    // --- Issue all global loads first: their DRAM latency hides both the
    // mbarrier-init cluster sync and everything up to the first bar. ---
    const float4 x4 = *reinterpret_cast<const float4*>(&data[(b0 + r) * FEAT + f0 + c * 4]);
    const float4 bb = *reinterpret_cast<const float4*>(&bias[f0 + c * 4]);
    const float  gb = __ldg(gbias);

    float4 v[16];
#pragma unroll
    for (int j = 0; j < 16; j++) {
        const int fl = fg * 16 + j;
        v[j] = *reinterpret_cast<const float4*>(&embed[(f0 + fl) * EDIM + d0]);
    }

    // Leader inits its combine mbarrier (7 producer arrivals flip parity 0).
    if (rank == 0 && tid == 0) {
        const uint32_t a = smem_u32(&mbar);
        asm volatile("mbarrier.init.shared.b64 [%0], %1;" :: "r"(a), "r"(7u) : "memory");
    }
    // Cluster sync publishes the init before any producer can arrive on it.
    // Runs while the LDGs above are still in flight -> off the critical path.
    asm volatile("barrier.cluster.arrive.aligned;" ::: "memory");
    asm volatile("barrier.cluster.wait.aligned;"   ::: "memory");

    // --- Stage x into shared + fold the bias dot-product (linear term). ---
    *reinterpret_cast<float4*>(&sh_x[r][c * 4]) = x4;
    {
        float p = x4.x * bb.x + x4.y * bb.y + x4.z * bb.z + x4.w * bb.w;
#pragma unroll
        for (int o = 16; o; o >>= 1) p += __shfl_xor_sync(0xffffffffu, p, o);
        if ((tid & 31) == 0) linT[r][(tid >> 5) & 1] = p;
    }
    __syncthreads();

    // --- Partial GEMM from registers: each prefetched float4 feeds 16 FFMA. ---
    float acc[NB_ROWS][4];
#pragma unroll
    for (int rr = 0; rr < NB_ROWS; rr++)
#pragma unroll
        for (int i = 0; i < 4; i++) acc[rr][i] = 0.0f;

#pragma unroll
    for (int j = 0; j < 16; j++) {
        const int fl = fg * 16 + j;
#pragma unroll
        for (int rr = 0; rr < NB_ROWS; rr++) {
            const float xf = sh_x[rr][fl];
            acc[rr][0] = fmaf(xf, v[j].x, acc[rr][0]);
            acc[rr][1] = fmaf(xf, v[j].y, acc[rr][1]);
            acc[rr][2] = fmaf(xf, v[j].z, acc[rr][2]);
            acc[rr][3] = fmaf(xf, v[j].w, acc[rr][3]);
        }
    }

#pragma unroll
    for (int rr = 0; rr < NB_ROWS; rr++) {
        float4 w;
        w.x = acc[rr][0]; w.y = acc[rr][1]; w.z = acc[rr][2]; w.w = acc[rr][3];
        *reinterpret_cast<float4*>(&shp[fg][rr][d0]) = w;
    }
    __syncthreads();

    // --- Cross-fg reduce -> partial S; ship to leader (plain STS if leader). ---
    {
        float s = 0.0f;
#pragma unroll
        for (int g = 0; g < 16; g++) s += shp[g][r][c];
        if (rank == 0) red_S[fc][r][c] = s;
        else           dsmem_st_leader_f32(smem_u32(&red_S[fc][r][c]), s);
    }
    if (tid < NB_ROWS) {
        const float l = linT[tid][0] + linT[tid][1];
        if (rank == 0) red_L[fc][tid] = l;
        else           dsmem_st_leader_f32(smem_u32(&red_L[fc][tid]), l);
    }

    // --- Combine handshake. Producers: CTA-wide sync (orders every thread's
    // DSMEM stores into tid0, cumulativity), single release-arrive, exit.
    // Leader: sync its own STS, then acquire-wait for the 7 arrivals. ---
    __syncthreads();
    if (rank != 0) {
        if (tid == 0) mbar_arrive_leader(smem_u32(&mbar));
        return;
    }
    mbar_wait_p0_cluster(smem_u32(&mbar));

    // --- Leader epilogue: combine 8 chunk-partials, square-sum over d,
    // add linear + global bias, sigmoid. ---
    {
        float s = 0.0f;
#pragma unroll
        for (int k = 0; k < CLUSTER; k++) s += red_S[k][r][c];
        float sq = s * s;
#pragma unroll
        for (int o = 16; o; o >>= 1) sq += __shfl_xor_sync(0xffffffffu, sq, o);
        if ((tid & 31) == 0) fin[r][(tid >> 5) & 1] = sq;
    }
    __syncthreads();

    if (tid < NB_ROWS) {
        float lin = 0.0f;
#pragma unroll
        for (int k = 0; k < CLUSTER; k++) lin += red_L[k][tid];
        const float z = gb + lin + fin[tid][0] + fin[tid][1];
        out[b0 + tid] = 1.0f / (1.0f + __expf(-z));
    }
}

extern "C" void kernel_launch(void* const* d_in, const int* in_sizes, int n_in,
                              void* d_out, int out_size) {
    const float* data  = (const float*)d_in[0];
    const float* embed = (const float*)d_in[1];
    const float* bias  = (const float*)d_in[2];
    const float* gbias = (const float*)d_in[3];
    float* out = (float*)d_out;

    fm_cluster<<<GRID, NTHREADS>>>(data, embed, bias, gbias, out);
}